// round 9
// baseline (speedup 1.0000x reference)
#include <cuda_runtime.h>

// Cubic clamped B-spline: 64 ctrl pts, knots = [0,0,0, linspace(0,1,62), 1,1,1].
// Piecewise cubic on 61 uniform spans; per-block coefficient table in local
// coord v = 61*x - span; each point = 1 LDS.128 + 3-FMA Horner.
// R9 = R8 (magic floor, unguarded exact-fit loop, closed-form prologue,
// single-wave 256x7) + 8x-replicated coefficient table (128B span stride,
// replica = lane&7) so every LDS.128 phase is conflict-free by construction.

#define N_SPAN  61
#define THREADS 256
#define VPT     2              // float4 groups per thread (8 points)
#define MAGIC   8388608.0f     // 2^23
#define MAGIC_BITS 0x4B000000

__device__ __forceinline__ float knot_at(int i) {
    float v = (float)(i - 3) * (1.0f / 61.0f);
    return fminf(fmaxf(v, 0.0f), 1.0f);
}

template <bool GUARD>
__global__ __launch_bounds__(THREADS, 7) void spline_eval_kernel(
        const float* __restrict__ x_,
        const float* __restrict__ ctrl,
        float* __restrict__ out,
        int n4)                      // number of float4 groups
{
    __shared__ float4 s_coef[N_SPAN * 8];    // 8 replicas per span, 128B stride

    const int tid = threadIdx.x;
    const int stride4 = gridDim.x * THREADS;
    const int g = blockIdx.x * THREADS + tid;
    const int oct16 = (tid & 7) << 4;        // replica byte offset for this lane

    // ---- issue all global x loads FIRST (independent, MLP=VPT) ----
    float4 xv[VPT];
    #pragma unroll
    for (int k = 0; k < VPT; k++) {
        const int i4 = g + k * stride4;
        if (!GUARD || i4 < n4)
            xv[k] = *reinterpret_cast<const float4*>(x_ + ((size_t)i4 << 2));
    }

    // ---- per-block coefficient table: tid = span (0..60), j = 3 + tid ----
    if (tid < N_SPAN) {
        const int   j    = 3 + tid;
        const float base = (float)tid * (1.0f / 61.0f);   // t[j]
        const float h    = 1.0f / 61.0f;

        const float c0 = ctrl[j - 3];
        const float c1 = ctrl[j - 2];
        const float c2 = ctrl[j - 1];
        const float c3 = ctrl[j];

        // closed-form reciprocal denominators (clamped uniform knots)
        const float I1H = 61.0f, I2H = 30.5f, I3H = 61.0f / 3.0f;
        const float i1  = I1H;
        const float i2a = (j == 3)  ? I1H : I2H;
        const float i2b = (j == 63) ? I1H : I2H;
        const float i3a = (j == 3)  ? I1H : ((j == 4)  ? I2H : I3H);
        const float i3b = (j == 3 || j == 63) ? I2H : I3H;
        const float i3c = (j == 63) ? I1H : ((j == 62) ? I2H : I3H);

        const float tjm2 = knot_at(j - 2), tjm1 = knot_at(j - 1);
        const float tj   = base;
        const float tj1  = knot_at(j + 1), tj2 = knot_at(j + 2), tj3 = knot_at(j + 3);

        float A, B;
        // degree 1: linear polys in v  (x = base + h*v)
        const float p10a = (tj1 - base) * i1, p10b = -h * i1;
        const float p11a = (base - tj)  * i1, p11b =  h * i1;
        // degree 2
        A = (tj1 - base) * i2a; B = -h * i2a;
        float p20_0 = A * p10a, p20_1 = A * p10b + B * p10a, p20_2 = B * p10b;
        A = (base - tjm1) * i2a; B = h * i2a;
        float p21_0 = A * p10a, p21_1 = A * p10b + B * p10a, p21_2 = B * p10b;
        A = (tj2 - base) * i2b; B = -h * i2b;
        p21_0 += A * p11a; p21_1 += A * p11b + B * p11a; p21_2 += B * p11b;
        A = (base - tj) * i2b; B = h * i2b;
        float p22_0 = A * p11a, p22_1 = A * p11b + B * p11a, p22_2 = B * p11b;
        // degree 3
        A = (tj1 - base) * i3a; B = -h * i3a;
        float p30_0 = A * p20_0;
        float p30_1 = A * p20_1 + B * p20_0;
        float p30_2 = A * p20_2 + B * p20_1;
        float p30_3 = B * p20_2;
        A = (base - tjm2) * i3a; B = h * i3a;
        float p31_0 = A * p20_0;
        float p31_1 = A * p20_1 + B * p20_0;
        float p31_2 = A * p20_2 + B * p20_1;
        float p31_3 = B * p20_2;
        A = (tj2 - base) * i3b; B = -h * i3b;
        p31_0 += A * p21_0; p31_1 += A * p21_1 + B * p21_0;
        p31_2 += A * p21_2 + B * p21_1; p31_3 += B * p21_2;
        A = (base - tjm1) * i3b; B = h * i3b;
        float p32_0 = A * p21_0;
        float p32_1 = A * p21_1 + B * p21_0;
        float p32_2 = A * p21_2 + B * p21_1;
        float p32_3 = B * p21_2;
        A = (tj3 - base) * i3c; B = -h * i3c;
        p32_0 += A * p22_0; p32_1 += A * p22_1 + B * p22_0;
        p32_2 += A * p22_2 + B * p22_1; p32_3 += B * p22_2;
        A = (base - tj) * i3c; B = h * i3c;
        float p33_0 = A * p22_0;
        float p33_1 = A * p22_1 + B * p22_0;
        float p33_2 = A * p22_2 + B * p22_1;
        float p33_3 = B * p22_2;

        float4 cf;
        cf.x = c0 * p30_0 + c1 * p31_0 + c2 * p32_0 + c3 * p33_0;
        cf.y = c0 * p30_1 + c1 * p31_1 + c2 * p32_1 + c3 * p33_1;
        cf.z = c0 * p30_2 + c1 * p31_2 + c2 * p32_2 + c3 * p33_2;
        cf.w = c0 * p30_3 + c1 * p31_3 + c2 * p32_3 + c3 * p33_3;

        float4* dst = &s_coef[tid << 3];
        #pragma unroll
        for (int p = 0; p < 8; p++) dst[p] = cf;       // 8 replicas, 16B apart
    }
    __syncthreads();

    const char* coef_base = reinterpret_cast<const char*>(s_coef) + oct16;

    // ---- evaluate VPT independent float4 groups ----
    #pragma unroll
    for (int k = 0; k < VPT; k++) {
        const int i4 = g + k * stride4;
        if (GUARD && i4 >= n4) continue;
        float pv[4] = {xv[k].x, xv[k].y, xv[k].z, xv[k].w};
        float yv[4];
        #pragma unroll
        for (int q = 0; q < 4; q++) {
            const float s = pv[q] * 61.0f;                 // s in [0, 61)
            const float fbig = __fadd_rz(s, MAGIC);        // 2^23 + floor(s)
            int jq = __float_as_int(fbig) - MAGIC_BITS;    // floor(s) as int
            jq = (jq > 60) ? 60 : jq;                      // addr safety
            const float fj = fbig - MAGIC;                 // floor(s) as float
            const float v  = s - fj;
            const float4 cf = *reinterpret_cast<const float4*>(coef_base + (jq << 7));
            yv[q] = fmaf(fmaf(fmaf(cf.w, v, cf.z), v, cf.y), v, cf.x);
        }
        float4 o;
        o.x = yv[0]; o.y = yv[1]; o.z = yv[2]; o.w = yv[3];
        *reinterpret_cast<float4*>(out + ((size_t)i4 << 2)) = o;
    }
}

extern "C" void kernel_launch(void* const* d_in, const int* in_sizes, int n_in,
                              void* d_out, int out_size)
{
    const float* x_   = (const float*)d_in[0];
    const float* ctrl = (const float*)d_in[2];
    float* out = (float*)d_out;

    const int n  = out_size;                  // 2097152
    const int n4 = n >> 2;                    // 524288 float4 groups
    const int blocks = (n4 + THREADS * VPT - 1) / (THREADS * VPT);   // 1024

    if ((n & 3) == 0 && blocks * THREADS * VPT == n4) {
        spline_eval_kernel<false><<<blocks, THREADS>>>(x_, ctrl, out, n4);
    } else {
        spline_eval_kernel<true><<<blocks, THREADS>>>(x_, ctrl, out, n4);
    }
}

// round 10
// speedup vs baseline: 1.1025x; 1.1025x over previous
#include <cuda_runtime.h>

// Cubic clamped B-spline: 64 ctrl pts, knots = [0,0,0, linspace(0,1,62), 1,1,1].
// Piecewise cubic on 61 uniform spans; per-block coefficient table in local
// coord v = 61*x - span; each point = 1 LDS.128 + 3-FMA Horner.
// R9 = R8 (magic floor, unguarded exact-fit loop, closed-form prologue,
// single-wave 256x7) + 8x-replicated coefficient table (128B span stride,
// replica = lane&7) so every LDS.128 phase is conflict-free by construction.

#define N_SPAN  61
#define THREADS 256
#define VPT     2              // float4 groups per thread (8 points)
#define MAGIC   8388608.0f     // 2^23
#define MAGIC_BITS 0x4B000000

__device__ __forceinline__ float knot_at(int i) {
    float v = (float)(i - 3) * (1.0f / 61.0f);
    return fminf(fmaxf(v, 0.0f), 1.0f);
}

template <bool GUARD>
__global__ __launch_bounds__(THREADS, 7) void spline_eval_kernel(
        const float* __restrict__ x_,
        const float* __restrict__ ctrl,
        float* __restrict__ out,
        int n4)                      // number of float4 groups
{
    __shared__ float4 s_coef[N_SPAN * 8];    // 8 replicas per span, 128B stride

    const int tid = threadIdx.x;
    const int stride4 = gridDim.x * THREADS;
    const int g = blockIdx.x * THREADS + tid;
    const int oct16 = (tid & 7) << 4;        // replica byte offset for this lane

    // ---- issue all global x loads FIRST (independent, MLP=VPT) ----
    float4 xv[VPT];
    #pragma unroll
    for (int k = 0; k < VPT; k++) {
        const int i4 = g + k * stride4;
        if (!GUARD || i4 < n4)
            xv[k] = *reinterpret_cast<const float4*>(x_ + ((size_t)i4 << 2));
    }

    // ---- per-block coefficient table: tid = span (0..60), j = 3 + tid ----
    if (tid < N_SPAN) {
        const int   j    = 3 + tid;
        const float base = (float)tid * (1.0f / 61.0f);   // t[j]
        const float h    = 1.0f / 61.0f;

        const float c0 = ctrl[j - 3];
        const float c1 = ctrl[j - 2];
        const float c2 = ctrl[j - 1];
        const float c3 = ctrl[j];

        // closed-form reciprocal denominators (clamped uniform knots)
        const float I1H = 61.0f, I2H = 30.5f, I3H = 61.0f / 3.0f;
        const float i1  = I1H;
        const float i2a = (j == 3)  ? I1H : I2H;
        const float i2b = (j == 63) ? I1H : I2H;
        const float i3a = (j == 3)  ? I1H : ((j == 4)  ? I2H : I3H);
        const float i3b = (j == 3 || j == 63) ? I2H : I3H;
        const float i3c = (j == 63) ? I1H : ((j == 62) ? I2H : I3H);

        const float tjm2 = knot_at(j - 2), tjm1 = knot_at(j - 1);
        const float tj   = base;
        const float tj1  = knot_at(j + 1), tj2 = knot_at(j + 2), tj3 = knot_at(j + 3);

        float A, B;
        // degree 1: linear polys in v  (x = base + h*v)
        const float p10a = (tj1 - base) * i1, p10b = -h * i1;
        const float p11a = (base - tj)  * i1, p11b =  h * i1;
        // degree 2
        A = (tj1 - base) * i2a; B = -h * i2a;
        float p20_0 = A * p10a, p20_1 = A * p10b + B * p10a, p20_2 = B * p10b;
        A = (base - tjm1) * i2a; B = h * i2a;
        float p21_0 = A * p10a, p21_1 = A * p10b + B * p10a, p21_2 = B * p10b;
        A = (tj2 - base) * i2b; B = -h * i2b;
        p21_0 += A * p11a; p21_1 += A * p11b + B * p11a; p21_2 += B * p11b;
        A = (base - tj) * i2b; B = h * i2b;
        float p22_0 = A * p11a, p22_1 = A * p11b + B * p11a, p22_2 = B * p11b;
        // degree 3
        A = (tj1 - base) * i3a; B = -h * i3a;
        float p30_0 = A * p20_0;
        float p30_1 = A * p20_1 + B * p20_0;
        float p30_2 = A * p20_2 + B * p20_1;
        float p30_3 = B * p20_2;
        A = (base - tjm2) * i3a; B = h * i3a;
        float p31_0 = A * p20_0;
        float p31_1 = A * p20_1 + B * p20_0;
        float p31_2 = A * p20_2 + B * p20_1;
        float p31_3 = B * p20_2;
        A = (tj2 - base) * i3b; B = -h * i3b;
        p31_0 += A * p21_0; p31_1 += A * p21_1 + B * p21_0;
        p31_2 += A * p21_2 + B * p21_1; p31_3 += B * p21_2;
        A = (base - tjm1) * i3b; B = h * i3b;
        float p32_0 = A * p21_0;
        float p32_1 = A * p21_1 + B * p21_0;
        float p32_2 = A * p21_2 + B * p21_1;
        float p32_3 = B * p21_2;
        A = (tj3 - base) * i3c; B = -h * i3c;
        p32_0 += A * p22_0; p32_1 += A * p22_1 + B * p22_0;
        p32_2 += A * p22_2 + B * p22_1; p32_3 += B * p22_2;
        A = (base - tj) * i3c; B = h * i3c;
        float p33_0 = A * p22_0;
        float p33_1 = A * p22_1 + B * p22_0;
        float p33_2 = A * p22_2 + B * p22_1;
        float p33_3 = B * p22_2;

        float4 cf;
        cf.x = c0 * p30_0 + c1 * p31_0 + c2 * p32_0 + c3 * p33_0;
        cf.y = c0 * p30_1 + c1 * p31_1 + c2 * p32_1 + c3 * p33_1;
        cf.z = c0 * p30_2 + c1 * p31_2 + c2 * p32_2 + c3 * p33_2;
        cf.w = c0 * p30_3 + c1 * p31_3 + c2 * p32_3 + c3 * p33_3;

        float4* dst = &s_coef[tid << 3];
        #pragma unroll
        for (int p = 0; p < 8; p++) dst[p] = cf;       // 8 replicas, 16B apart
    }
    __syncthreads();

    const char* coef_base = reinterpret_cast<const char*>(s_coef) + oct16;

    // ---- evaluate VPT independent float4 groups ----
    #pragma unroll
    for (int k = 0; k < VPT; k++) {
        const int i4 = g + k * stride4;
        if (GUARD && i4 >= n4) continue;
        float pv[4] = {xv[k].x, xv[k].y, xv[k].z, xv[k].w};
        float yv[4];
        #pragma unroll
        for (int q = 0; q < 4; q++) {
            const float s = pv[q] * 61.0f;                 // s in [0, 61)
            const float fbig = __fadd_rz(s, MAGIC);        // 2^23 + floor(s)
            int jq = __float_as_int(fbig) - MAGIC_BITS;    // floor(s) as int
            jq = (jq > 60) ? 60 : jq;                      // addr safety
            const float fj = fbig - MAGIC;                 // floor(s) as float
            const float v  = s - fj;
            const float4 cf = *reinterpret_cast<const float4*>(coef_base + (jq << 7));
            yv[q] = fmaf(fmaf(fmaf(cf.w, v, cf.z), v, cf.y), v, cf.x);
        }
        float4 o;
        o.x = yv[0]; o.y = yv[1]; o.z = yv[2]; o.w = yv[3];
        *reinterpret_cast<float4*>(out + ((size_t)i4 << 2)) = o;
    }
}

extern "C" void kernel_launch(void* const* d_in, const int* in_sizes, int n_in,
                              void* d_out, int out_size)
{
    const float* x_   = (const float*)d_in[0];
    const float* ctrl = (const float*)d_in[2];
    float* out = (float*)d_out;

    const int n  = out_size;                  // 2097152
    const int n4 = n >> 2;                    // 524288 float4 groups
    const int blocks = (n4 + THREADS * VPT - 1) / (THREADS * VPT);   // 1024

    if ((n & 3) == 0 && blocks * THREADS * VPT == n4) {
        spline_eval_kernel<false><<<blocks, THREADS>>>(x_, ctrl, out, n4);
    } else {
        spline_eval_kernel<true><<<blocks, THREADS>>>(x_, ctrl, out, n4);
    }
}

// round 11
// speedup vs baseline: 1.2000x; 1.0885x over previous
#include <cuda_runtime.h>

// Cubic clamped B-spline: 64 ctrl pts, knots = [0,0,0, linspace(0,1,62), 1,1,1].
// Piecewise cubic on 61 uniform spans; per-block coefficient table in local
// coord v = 61*x - span; each point = 1 LDS.128 + 3-FMA Horner.
// R9 = R8 (magic floor, unguarded exact-fit loop, closed-form prologue,
// single-wave 256x7) + 8x-replicated coefficient table (128B span stride,
// replica = lane&7) so every LDS.128 phase is conflict-free by construction.

#define N_SPAN  61
#define THREADS 256
#define VPT     2              // float4 groups per thread (8 points)
#define MAGIC   8388608.0f     // 2^23
#define MAGIC_BITS 0x4B000000

__device__ __forceinline__ float knot_at(int i) {
    float v = (float)(i - 3) * (1.0f / 61.0f);
    return fminf(fmaxf(v, 0.0f), 1.0f);
}

template <bool GUARD>
__global__ __launch_bounds__(THREADS, 7) void spline_eval_kernel(
        const float* __restrict__ x_,
        const float* __restrict__ ctrl,
        float* __restrict__ out,
        int n4)                      // number of float4 groups
{
    __shared__ float4 s_coef[N_SPAN * 8];    // 8 replicas per span, 128B stride

    const int tid = threadIdx.x;
    const int stride4 = gridDim.x * THREADS;
    const int g = blockIdx.x * THREADS + tid;
    const int oct16 = (tid & 7) << 4;        // replica byte offset for this lane

    // ---- issue all global x loads FIRST (independent, MLP=VPT) ----
    float4 xv[VPT];
    #pragma unroll
    for (int k = 0; k < VPT; k++) {
        const int i4 = g + k * stride4;
        if (!GUARD || i4 < n4)
            xv[k] = *reinterpret_cast<const float4*>(x_ + ((size_t)i4 << 2));
    }

    // ---- per-block coefficient table: tid = span (0..60), j = 3 + tid ----
    if (tid < N_SPAN) {
        const int   j    = 3 + tid;
        const float base = (float)tid * (1.0f / 61.0f);   // t[j]
        const float h    = 1.0f / 61.0f;

        const float c0 = ctrl[j - 3];
        const float c1 = ctrl[j - 2];
        const float c2 = ctrl[j - 1];
        const float c3 = ctrl[j];

        // closed-form reciprocal denominators (clamped uniform knots)
        const float I1H = 61.0f, I2H = 30.5f, I3H = 61.0f / 3.0f;
        const float i1  = I1H;
        const float i2a = (j == 3)  ? I1H : I2H;
        const float i2b = (j == 63) ? I1H : I2H;
        const float i3a = (j == 3)  ? I1H : ((j == 4)  ? I2H : I3H);
        const float i3b = (j == 3 || j == 63) ? I2H : I3H;
        const float i3c = (j == 63) ? I1H : ((j == 62) ? I2H : I3H);

        const float tjm2 = knot_at(j - 2), tjm1 = knot_at(j - 1);
        const float tj   = base;
        const float tj1  = knot_at(j + 1), tj2 = knot_at(j + 2), tj3 = knot_at(j + 3);

        float A, B;
        // degree 1: linear polys in v  (x = base + h*v)
        const float p10a = (tj1 - base) * i1, p10b = -h * i1;
        const float p11a = (base - tj)  * i1, p11b =  h * i1;
        // degree 2
        A = (tj1 - base) * i2a; B = -h * i2a;
        float p20_0 = A * p10a, p20_1 = A * p10b + B * p10a, p20_2 = B * p10b;
        A = (base - tjm1) * i2a; B = h * i2a;
        float p21_0 = A * p10a, p21_1 = A * p10b + B * p10a, p21_2 = B * p10b;
        A = (tj2 - base) * i2b; B = -h * i2b;
        p21_0 += A * p11a; p21_1 += A * p11b + B * p11a; p21_2 += B * p11b;
        A = (base - tj) * i2b; B = h * i2b;
        float p22_0 = A * p11a, p22_1 = A * p11b + B * p11a, p22_2 = B * p11b;
        // degree 3
        A = (tj1 - base) * i3a; B = -h * i3a;
        float p30_0 = A * p20_0;
        float p30_1 = A * p20_1 + B * p20_0;
        float p30_2 = A * p20_2 + B * p20_1;
        float p30_3 = B * p20_2;
        A = (base - tjm2) * i3a; B = h * i3a;
        float p31_0 = A * p20_0;
        float p31_1 = A * p20_1 + B * p20_0;
        float p31_2 = A * p20_2 + B * p20_1;
        float p31_3 = B * p20_2;
        A = (tj2 - base) * i3b; B = -h * i3b;
        p31_0 += A * p21_0; p31_1 += A * p21_1 + B * p21_0;
        p31_2 += A * p21_2 + B * p21_1; p31_3 += B * p21_2;
        A = (base - tjm1) * i3b; B = h * i3b;
        float p32_0 = A * p21_0;
        float p32_1 = A * p21_1 + B * p21_0;
        float p32_2 = A * p21_2 + B * p21_1;
        float p32_3 = B * p21_2;
        A = (tj3 - base) * i3c; B = -h * i3c;
        p32_0 += A * p22_0; p32_1 += A * p22_1 + B * p22_0;
        p32_2 += A * p22_2 + B * p22_1; p32_3 += B * p22_2;
        A = (base - tj) * i3c; B = h * i3c;
        float p33_0 = A * p22_0;
        float p33_1 = A * p22_1 + B * p22_0;
        float p33_2 = A * p22_2 + B * p22_1;
        float p33_3 = B * p22_2;

        float4 cf;
        cf.x = c0 * p30_0 + c1 * p31_0 + c2 * p32_0 + c3 * p33_0;
        cf.y = c0 * p30_1 + c1 * p31_1 + c2 * p32_1 + c3 * p33_1;
        cf.z = c0 * p30_2 + c1 * p31_2 + c2 * p32_2 + c3 * p33_2;
        cf.w = c0 * p30_3 + c1 * p31_3 + c2 * p32_3 + c3 * p33_3;

        float4* dst = &s_coef[tid << 3];
        #pragma unroll
        for (int p = 0; p < 8; p++) dst[p] = cf;       // 8 replicas, 16B apart
    }
    __syncthreads();

    const char* coef_base = reinterpret_cast<const char*>(s_coef) + oct16;

    // ---- evaluate VPT independent float4 groups ----
    #pragma unroll
    for (int k = 0; k < VPT; k++) {
        const int i4 = g + k * stride4;
        if (GUARD && i4 >= n4) continue;
        float pv[4] = {xv[k].x, xv[k].y, xv[k].z, xv[k].w};
        float yv[4];
        #pragma unroll
        for (int q = 0; q < 4; q++) {
            const float s = pv[q] * 61.0f;                 // s in [0, 61)
            const float fbig = __fadd_rz(s, MAGIC);        // 2^23 + floor(s)
            int jq = __float_as_int(fbig) - MAGIC_BITS;    // floor(s) as int
            jq = (jq > 60) ? 60 : jq;                      // addr safety
            const float fj = fbig - MAGIC;                 // floor(s) as float
            const float v  = s - fj;
            const float4 cf = *reinterpret_cast<const float4*>(coef_base + (jq << 7));
            yv[q] = fmaf(fmaf(fmaf(cf.w, v, cf.z), v, cf.y), v, cf.x);
        }
        float4 o;
        o.x = yv[0]; o.y = yv[1]; o.z = yv[2]; o.w = yv[3];
        *reinterpret_cast<float4*>(out + ((size_t)i4 << 2)) = o;
    }
}

extern "C" void kernel_launch(void* const* d_in, const int* in_sizes, int n_in,
                              void* d_out, int out_size)
{
    const float* x_   = (const float*)d_in[0];
    const float* ctrl = (const float*)d_in[2];
    float* out = (float*)d_out;

    const int n  = out_size;                  // 2097152
    const int n4 = n >> 2;                    // 524288 float4 groups
    const int blocks = (n4 + THREADS * VPT - 1) / (THREADS * VPT);   // 1024

    if ((n & 3) == 0 && blocks * THREADS * VPT == n4) {
        spline_eval_kernel<false><<<blocks, THREADS>>>(x_, ctrl, out, n4);
    } else {
        spline_eval_kernel<true><<<blocks, THREADS>>>(x_, ctrl, out, n4);
    }
}